// round 16
// baseline (speedup 1.0000x reference)
#include <cuda_runtime.h>

// HolographicLayer: eta = dot(R[p], ccorr_half(E[s], E[o]))
//   ccorr_half(a,b)[k] = sum_i a[k+i-100] * b[i], zero-padded, d=201
// With padded smem sp (sp[100+j] = a[j], zeros elsewhere):
//   eta = sum_k rv[k] * sum_i sp[k+i] * bv[i]
// Single block, 512 threads. Thread t owns a 4-k x 24-i register tile:
//   tc = t/51 (i-chunk 0..10, chunks 9-10 are zero-padding), tk = t%51.
// Halved per-thread serial work vs the 256-thread variant: 6 loop
// iterations, <=1 LDG+STS per thread in the fill, 16 warps for latency
// hiding. Sliding-window sp loads, scalar FFMA, 4 accumulators.

#define D      201
#define PAD    100
#define NT     512
#define CHUNK  24
#define SPLEN  480    // max sp index touched: 200+240+27 = 467
#define BVLEN  264    // max bv index touched: 240+23    = 263

__global__ void __launch_bounds__(NT, 1)
holo_kernel(const int* __restrict__ x,
            const float* __restrict__ E,
            const float* __restrict__ R,
            float* __restrict__ out) {
    __shared__ __align__(16) float sp[SPLEN];
    __shared__ __align__(16) float bv[BVLEN];
    __shared__ __align__(16) float wsum[NT / 32];

    const int t = threadIdx.x;

    // x is [32,3] row-major; row 0 = (s, o, p). One 16B load grabs all
    // three indices (harness buffers are 16B-aligned; x[3] is don't-care).
    const int4 xi = *reinterpret_cast<const int4*>(x);
    const int s = xi.x, o = xi.y, p = xi.z;
    const float* __restrict__ Es = E + (long long)s * D;
    const float* __restrict__ Eo = E + (long long)o * D;
    const float* __restrict__ Rp = R + (long long)p * D;

    // 51 k-groups x 9 live i-chunks (24 wide, covering i<216; bv zero-
    // padded beyond 201). tc = 9,10 land entirely in bv==0 territory.
    const int tc = t / 51;            // i-chunk: 0..10
    const int tk = t - tc * 51;       // k-group: 0..50
    const int k0 = tk * 4;            // multiple of 4 (16B aligned)
    const int ci = tc * CHUNK;        // multiple of 8

    // Early per-thread R gathers; consumed only after the compute loop.
    // Guarded: k0+c can reach 203 > 200 (OOB on the last R row).
    const float r0 = Rp[k0];
    const float r1 = (k0 + 1 < D) ? Rp[k0 + 1] : 0.0f;
    const float r2 = (k0 + 2 < D) ? Rp[k0 + 2] : 0.0f;
    const float r3 = (k0 + 3 < D) ? Rp[k0 + 3] : 0.0f;

    // Fill: at most ONE sp element and ONE bv element per thread.
    if (t < SPLEN) sp[t] = (t >= PAD && t < PAD + D) ? Es[t - PAD] : 0.0f;
    if (t < BVLEN) bv[t] = (t < D) ? Eo[t] : 0.0f;
    __syncthreads();

    // 4 accumulators break the FMA chain; sliding-window sp loads.
    float a0 = 0.0f, a1 = 0.0f, a2 = 0.0f, a3 = 0.0f;
    float4 s0 = *reinterpret_cast<const float4*>(&sp[k0 + ci]);
    #pragma unroll
    for (int j = 0; j < CHUNK; j += 4) {
        const float4 s1 = *reinterpret_cast<const float4*>(&sp[k0 + ci + j + 4]);
        const float4 b4 = *reinterpret_cast<const float4*>(&bv[ci + j]);

        a0 = fmaf(s0.x, b4.x, a0); a0 = fmaf(s0.y, b4.y, a0);
        a0 = fmaf(s0.z, b4.z, a0); a0 = fmaf(s0.w, b4.w, a0);

        a1 = fmaf(s0.y, b4.x, a1); a1 = fmaf(s0.z, b4.y, a1);
        a1 = fmaf(s0.w, b4.z, a1); a1 = fmaf(s1.x, b4.w, a1);

        a2 = fmaf(s0.z, b4.x, a2); a2 = fmaf(s0.w, b4.y, a2);
        a2 = fmaf(s1.x, b4.z, a2); a2 = fmaf(s1.y, b4.w, a2);

        a3 = fmaf(s0.w, b4.x, a3); a3 = fmaf(s1.x, b4.y, a3);
        a3 = fmaf(s1.y, b4.z, a3); a3 = fmaf(s1.z, b4.w, a3);

        s0 = s1;
    }

    // Fold in rv (zero-work chunks' accumulators are all zero).
    float v = r0 * a0;
    v = fmaf(r1, a1, v);
    v = fmaf(r2, a2, v);
    v = fmaf(r3, a3, v);

    // Warp reduce, then thread 0 sums the 16 warp partials serially
    // (4x LDS.128 + 15 adds beats a second shfl stage at 26 cyc/shfl).
    #pragma unroll
    for (int off = 16; off > 0; off >>= 1)
        v += __shfl_down_sync(0xFFFFFFFFu, v, off);
    if ((t & 31) == 0) wsum[t >> 5] = v;
    __syncthreads();

    if (t == 0) {
        const float4 w0 = *reinterpret_cast<const float4*>(&wsum[0]);
        const float4 w1 = *reinterpret_cast<const float4*>(&wsum[4]);
        const float4 w2 = *reinterpret_cast<const float4*>(&wsum[8]);
        const float4 w3 = *reinterpret_cast<const float4*>(&wsum[12]);
        out[0] = (((w0.x + w0.y) + (w0.z + w0.w))
               +  ((w1.x + w1.y) + (w1.z + w1.w)))
               + (((w2.x + w2.y) + (w2.z + w2.w))
               +  ((w3.x + w3.y) + (w3.z + w3.w)));
    }
}

extern "C" void kernel_launch(void* const* d_in, const int* in_sizes, int n_in,
                              void* d_out, int out_size) {
    const int*   x = (const int*)d_in[0];
    const float* E = (const float*)d_in[1];
    const float* R = (const float*)d_in[2];
    float* out = (float*)d_out;
    holo_kernel<<<1, NT>>>(x, E, R, out);
}